// round 2
// baseline (speedup 1.0000x reference)
#include <cuda_runtime.h>
#include <math.h>

#define THREADS 512
#define NFFT 1024
#define NPAIRS 28
#define T_DIM 250
#define B_DIM 16
#define M_DIM 8

__constant__ int c_i1[NPAIRS] = {0,0,0,0,0,0,0,1,1,1,1,1,1,2,2,2,2,2,3,3,3,3,4,4,4,5,5,6};
__constant__ int c_i2[NPAIRS] = {1,2,3,4,5,6,7,2,3,4,5,6,7,3,4,5,6,7,4,5,6,7,5,6,7,6,7,7};

// Shared layout (floats):
//   Xre[8*1024], Xim[8*1024]  : channel spectra (bit-reversed after forward)
//   Wre[512], Wim[512]        : twiddles W[j] = exp(-2*pi*i*j/1024)
//   Rre[1024], Rim[1024]      : per-pair cross spectrum / inverse FFT workspace
// total = 19456 floats = 77824 bytes (dynamic)

__global__ __launch_bounds__(THREADS, 2)
void gcc_phat_fused_kernel(const float* __restrict__ x, float* __restrict__ out) {
    extern __shared__ float sm[];
    float* Xre = sm;                 // 8192
    float* Xim = Xre + 8192;         // 8192
    float* Wre = Xim + 8192;         // 512
    float* Wim = Wre + 512;          // 512
    float* Rre = Wim + 512;          // 1024
    float* Rim = Rre + 1024;         // 1024

    const int bt  = blockIdx.x;
    const int b   = bt / T_DIM;
    const int t   = bt % T_DIM;
    const int tid = threadIdx.x;

    // ---- load 8 channels (coalesced), imag = 0 ----
    const float* xb = x + ((long)b * M_DIM * T_DIM + t) * NFFT;
    #pragma unroll
    for (int i = tid; i < M_DIM * NFFT; i += THREADS) {
        int c = i >> 10, idx = i & 1023;
        Xre[i] = xb[(long)c * T_DIM * NFFT + idx];
        Xim[i] = 0.f;
    }

    // ---- twiddle table: W[j] = exp(-2*pi*i*j/1024), j in [0,512) ----
    {
        float ang = -2.f * 3.14159265358979323846f * (float)tid * (1.f / 1024.f);
        float s, c;
        sincosf(ang, &s, &c);
        Wre[tid] = c; Wim[tid] = s;
    }
    __syncthreads();

    // ---- forward DIF radix-2 FFTs (natural in -> bit-reversed out), all 8
    //      channels per stage so only 10 barriers total ----
    for (int s = 9; s >= 0; --s) {
        const int h    = 1 << s;
        const int mult = 512 >> s;             // N/(2h)
        const int j    = tid & (h - 1);
        const int base = ((tid ^ j) << 1) | j; // grp*2h + j
        const float wr = Wre[j * mult];
        const float wi = Wim[j * mult];
        #pragma unroll
        for (int c = 0; c < M_DIM; ++c) {
            float* re = Xre + (c << 10);
            float* im = Xim + (c << 10);
            float ar = re[base],     ai = im[base];
            float br = re[base + h], bi = im[base + h];
            re[base]     = ar + br;
            im[base]     = ai + bi;
            float dr = ar - br, di = ai - bi;
            re[base + h] = dr * wr - di * wi;
            im[base + h] = dr * wi + di * wr;
        }
        __syncthreads();
    }

    // ---- per pair: cross-spectrum + PHAT normalize (bit-rev order is fine,
    //      it's pointwise), then inverse DIT radix-2 (bit-rev -> natural) ----
    for (int p = 0; p < NPAIRS; ++p) {
        const float* X1r = Xre + (c_i1[p] << 10);
        const float* X1i = Xim + (c_i1[p] << 10);
        const float* X2r = Xre + (c_i2[p] << 10);
        const float* X2i = Xim + (c_i2[p] << 10);

        #pragma unroll
        for (int k = tid; k < NFFT; k += THREADS) {
            float ar = X1r[k], ai = X1i[k];
            float br = X2r[k], bi = X2i[k];
            float rr = ar * br + ai * bi;     // X1 * conj(X2)
            float ri = ai * br - ar * bi;
            float mag = sqrtf(rr * rr + ri * ri);
            float inv = __fdividef(1.f, mag + 1e-8f);
            Rre[k] = rr * inv;
            Rim[k] = ri * inv;
        }
        __syncthreads();

        for (int s = 0; s <= 9; ++s) {
            const int h    = 1 << s;
            const int mult = 512 >> s;
            const int j    = tid & (h - 1);
            const int base = ((tid ^ j) << 1) | j;
            const float wr =  Wre[j * mult];
            const float wi = -Wim[j * mult];  // conj for inverse
            float br = Rre[base + h], bi = Rim[base + h];
            float tr = br * wr - bi * wi;
            float ti = br * wi + bi * wr;
            float ar = Rre[base],     ai = Rim[base];
            Rre[base]     = ar + tr;
            Rim[base]     = ai + ti;
            Rre[base + h] = ar - tr;
            Rim[base + h] = ai - ti;
            __syncthreads();
        }

        // fftshift + center 64 lags: out[j] = cc[(992 + j) & 1023] / 1024
        if (tid < 64) {
            out[(((long)b * NPAIRS + p) * T_DIM + t) * 64 + tid] =
                Rre[(992 + tid) & 1023] * (1.f / 1024.f);
        }
        __syncthreads();  // protect Rre/Rim before next pair overwrites
    }
}

extern "C" void kernel_launch(void* const* d_in, const int* in_sizes, int n_in,
                              void* d_out, int out_size) {
    const float* x = (const float*)d_in[0];
    float* out = (float*)d_out;
    const int smem_bytes = 19456 * 4;  // 77824
    cudaFuncSetAttribute(gcc_phat_fused_kernel,
                         cudaFuncAttributeMaxDynamicSharedMemorySize, smem_bytes);
    gcc_phat_fused_kernel<<<B_DIM * T_DIM, THREADS, smem_bytes>>>(x, out);
}

// round 5
// speedup vs baseline: 2.7632x; 2.7632x over previous
#include <cuda_runtime.h>
#include <math.h>

#define THREADS 512
#define NFFT 1024
#define NPAIRS 28
#define T_DIM 250
#define B_DIM 16
#define M_DIM 8

// padded index: insert 1 float gap every 32 to kill transpose-pattern conflicts
#define PAD(i) ((i) + ((i) >> 5))

__constant__ int c_i1[NPAIRS] = {0,0,0,0,0,0,0,1,1,1,1,1,1,2,2,2,2,2,3,3,3,3,4,4,4,5,5,6};
__constant__ int c_i2[NPAIRS] = {1,2,3,4,5,6,7,2,3,4,5,6,7,3,4,5,6,7,4,5,6,7,5,6,7,6,7,7};

// Shared layout (floats):
//  Xre[8*1056], Xim[8*1056]   channel spectra, padded, digit-reversed slot order
//  C[1056]                    cos(2*pi*m/1024) at PAD(m)  (sin(t)=cos(t-pi/2) -> C[(m+768)&1023])
//  T32r[16], T32i[16]         e^{+2*pi*i*v/32} for the in-register 32-pt IDFTs
//  Sre[2*1056], Sim[2*1056]   S_q[r] for 2 pairs, layout [pair][r*33+q]
// total = 22208 floats = 88832 bytes

__global__ __launch_bounds__(THREADS, 2)
void gcc_phat_kernel(const float* __restrict__ x, float* __restrict__ out) {
    extern __shared__ float sm[];
    float* Xre  = sm;                  // 8448
    float* Xim  = Xre  + 8448;         // 8448
    float* C    = Xim  + 8448;         // 1056
    float* T32r = C    + 1056;         // 16
    float* T32i = T32r + 16;           // 16
    float* Sre  = T32i + 16;           // 2112
    float* Sim  = Sre  + 2112;         // 2112

    const int bt  = blockIdx.x;
    const int b   = bt / T_DIM;
    const int t   = bt % T_DIM;
    const int tid = threadIdx.x;
    const int lane = tid & 31;
    const int wrp  = tid >> 5;

    const float TWO_PI = 6.28318530717958647692f;

    // ---- tables ----
    #pragma unroll
    for (int i = 0; i < 2; ++i) {
        int m = tid + i * THREADS;
        C[PAD(m)] = cosf(TWO_PI * (float)m * (1.f / 1024.f));
    }
    if (tid < 16) {
        float ang = TWO_PI * (float)tid * (1.f / 32.f);   // +i direction (inverse)
        T32r[tid] = cosf(ang);
        T32i[tid] = sinf(ang);
    }

    // ---- load 8 channels (coalesced), imag = 0, natural time order ----
    const float* xb = x + ((long)b * M_DIM * T_DIM + t) * NFFT;
    #pragma unroll
    for (int i = tid; i < M_DIM * NFFT; i += THREADS) {
        int c = i >> 10, idx = i & 1023;
        Xre[c * 1056 + PAD(idx)] = xb[(long)c * T_DIM * NFFT + idx];
        Xim[c * 1056 + PAD(idx)] = 0.f;
    }
    __syncthreads();

    // ---- forward radix-4 DIF, in place, 5 stages; output digit-reversed ----
    // stage sub-size n = 4q; lq = log2(q) in {8,6,4,2,0}
    #pragma unroll
    for (int st = 0; st < 5; ++st) {
        const int lq = 8 - 2 * st;
        const int q  = 1 << lq;
        #pragma unroll
        for (int it = 0; it < 4; ++it) {
            int u   = it * THREADS + tid;
            int ch  = u >> 8;             // 0..7 (two channels per it over 512 thr)
            int bf  = u & 255;            // butterfly within channel
            int j   = bf & (q - 1);
            int grp = bf >> lq;
            int o   = (grp << (lq + 2)) + j;
            float* re = Xre + ch * 1056;
            float* im = Xim + ch * 1056;
            int A0 = PAD(o), A1 = PAD(o + q), A2 = PAD(o + 2 * q), A3 = PAD(o + 3 * q);
            float ar = re[A0], ai = im[A0];
            float br = re[A1], bi = im[A1];
            float cr = re[A2], ci = im[A2];
            float dr = re[A3], di = im[A3];
            float t0r = ar + cr, t0i = ai + ci;
            float t1r = ar - cr, t1i = ai - ci;
            float t2r = br + dr, t2i = bi + di;
            float t3r = bi - di, t3i = dr - br;     // -i*(b-d)
            // block 0
            re[A0] = t0r + t2r; im[A0] = t0i + t2i;
            float u1r = t1r + t3r, u1i = t1i + t3i; // -> *w1
            float u2r = t0r - t2r, u2i = t0i - t2i; // -> *w2
            float u3r = t1r - t3r, u3i = t1i - t3i; // -> *w3
            int   m1  = j << (8 - lq);              // j*1024/n
            float w1r = C[PAD(m1)];
            float w1i = -C[PAD((m1 + 768) & 1023)];
            float w2r = w1r * w1r - w1i * w1i;
            float w2i = 2.f * w1r * w1i;
            float w3r = w2r * w1r - w2i * w1i;
            float w3i = w2r * w1i + w2i * w1r;
            re[A1] = u1r * w1r - u1i * w1i; im[A1] = u1r * w1i + u1i * w1r;
            re[A2] = u2r * w2r - u2i * w2i; im[A2] = u2r * w2i + u2i * w2r;
            re[A3] = u3r * w3r - u3i * w3i; im[A3] = u3r * w3i + u3i * w3r;
        }
        __syncthreads();
    }

    // lane-dependent part of dr4(q+32*lane) and brev5(lane)
    const int drl = ((lane & 1) << 5) | ((lane & 6) << 1) | ((lane & 24) >> 3);
    const int brl = ((lane & 1) << 4) | ((lane & 2) << 2) | (lane & 4)
                  | ((lane & 8) >> 2) | ((lane & 16) >> 4);

    // ---- inverse: 2 pairs per iteration ----
    for (int p0 = 0; p0 < NPAIRS; p0 += 2) {
        // inner: 64 column-tasks (pair, q); warp handles 4
        #pragma unroll
        for (int it = 0; it < 4; ++it) {
            int tt = wrp * 4 + it;
            int pi = tt >> 5;
            int q  = tt & 31;
            int p  = p0 + pi;
            const float* X1r = Xre + c_i1[p] * 1056;
            const float* X1i = Xim + c_i1[p] * 1056;
            const float* X2r = Xre + c_i2[p] * 1056;
            const float* X2i = Xim + c_i2[p] * 1056;
            // natural freq k = q + 32*lane lives at digit-reversed slot dr4(k)
            int dq = ((q & 3) << 8) | ((q & 12) << 4) | (q & 16);
            int a  = dq + drl;
            int pa = PAD(a);
            float x1r = X1r[pa], x1i = X1i[pa];
            float x2r = X2r[pa], x2i = X2i[pa];
            // cross-spectrum + PHAT (in registers)
            float rr = x1r * x2r + x1i * x2i;
            float ri = x1i * x2r - x1r * x2i;
            float inv = rsqrtf(fmaxf(rr * rr + ri * ri, 1e-38f));
            float vr = rr * inv, vi = ri * inv;
            // 32-pt inverse DIF FFT across lanes via shuffles (output at brev5(lane))
            #pragma unroll
            for (int h = 16; h >= 1; h >>= 1) {
                float pr = __shfl_xor_sync(0xffffffffu, vr, h);
                float pq = __shfl_xor_sync(0xffffffffu, vi, h);
                int jj = lane & (h - 1);
                int v  = jj * (16 / h);
                float twr = T32r[v], twi = T32i[v];
                if (lane & h) {
                    float sr = pr - vr, si = pq - vi;
                    vr = sr * twr - si * twi;
                    vi = sr * twi + si * twr;
                } else {
                    vr += pr; vi += pq;
                }
            }
            Sre[pi * 1056 + brl * 33 + q] = vr;
            Sim[pi * 1056 + brl * 33 + q] = vi;
        }
        __syncthreads();

        // outer: 128 outputs (2 pairs x 64 lags), 4 threads per output
        {
            int out_i = tid >> 2;          // 0..127
            int qi    = tid & 3;
            int pi    = out_i >> 6;
            int n     = out_i & 63;
            int r     = n & 31;
            int lag   = n - 32;
            int q0    = qi * 8;
            int m0 = (q0 * lag + 16384) & 1023;
            int ms = (lag + 1024) & 1023;
            float wr = C[PAD(m0)], wi = C[PAD((m0 + 768) & 1023)];
            float sr = C[PAD(ms)], si = C[PAD((ms + 768) & 1023)];
            const float* SR = Sre + pi * 1056 + r * 33 + q0;
            const float* SI = Sim + pi * 1056 + r * 33 + q0;
            float acc = 0.f;
            #pragma unroll
            for (int s = 0; s < 8; ++s) {
                acc += SR[s] * wr - SI[s] * wi;
                float nwr = wr * sr - wi * si;   // advance twiddle by e^{+2pi*i*lag/1024}
                wi = wr * si + wi * sr;
                wr = nwr;
            }
            acc += __shfl_xor_sync(0xffffffffu, acc, 1);
            acc += __shfl_xor_sync(0xffffffffu, acc, 2);
            if (qi == 0) {
                int p = p0 + pi;
                out[(((long)b * NPAIRS + p) * T_DIM + t) * 64 + n] = acc * (1.f / 1024.f);
            }
        }
        __syncthreads();
    }
}

extern "C" void kernel_launch(void* const* d_in, const int* in_sizes, int n_in,
                              void* d_out, int out_size) {
    const float* x = (const float*)d_in[0];
    float* out = (float*)d_out;
    const int smem_bytes = 22208 * 4;   // 88832
    cudaFuncSetAttribute(gcc_phat_kernel,
                         cudaFuncAttributeMaxDynamicSharedMemorySize, smem_bytes);
    gcc_phat_kernel<<<B_DIM * T_DIM, THREADS, smem_bytes>>>(x, out);
}